// round 3
// baseline (speedup 1.0000x reference)
#include <cuda_runtime.h>
#include <math.h>

// Problem constants
#define B_ROWS 8192
#define IN_F   4096
#define OUT_F  4096
#define NFRAG  16
#define FS     256
#define COMP   1024

// Scratch (static device globals — no allocation)
__device__ float g_probs[B_ROWS * NFRAG];     // softmax gate probs  [B,16]
__device__ float g_comp [B_ROWS * COMP];      // compressed = masked @ Wc^T  [B,1024]

// ---------------------------------------------------------------------------
// Gating kernel: one block per row; 16 warps, warp f computes score for
// fragment f (dot of 256 elements), then softmax over the 16 scores.
// ---------------------------------------------------------------------------
__global__ void __launch_bounds__(512) gating_kernel(
    const float* __restrict__ x, const float* __restrict__ sel)
{
    int b = blockIdx.x;
    int t = threadIdx.x;
    int w = t >> 5;           // fragment id 0..15
    int lane = t & 31;

    const float* xr = x + (size_t)b * IN_F + w * FS;
    const float* sr = sel + w * FS;

    float acc = 0.f;
#pragma unroll
    for (int j = 0; j < 8; j++) {
        int i = lane + 32 * j;
        acc += xr[i] * sr[i];
    }
#pragma unroll
    for (int o = 16; o; o >>= 1)
        acc += __shfl_xor_sync(0xFFFFFFFFu, acc, o);

    __shared__ float s[NFRAG];
    if (lane == 0) s[w] = acc;
    __syncthreads();

    if (t < NFRAG) {
        float m = -INFINITY;
#pragma unroll
        for (int f = 0; f < NFRAG; f++) m = fmaxf(m, s[f]);
        float sum = 0.f;
#pragma unroll
        for (int f = 0; f < NFRAG; f++) sum += __expf(s[f] - m);
        g_probs[b * NFRAG + t] = __expf(s[t] - m) / sum;
    }
}

// ---------------------------------------------------------------------------
// SGEMM tiles: BM=BN=128, BK=16, 256 threads, 8x8 accumulators per thread.
// A is x scaled on the fly by p (or 1-p); with BK=16 the fragment id is
// constant over a K-tile, so the scale is one probs load per row per tile.
// ---------------------------------------------------------------------------
#define BM 128
#define BN 128
#define BK 16

// C1[b, n] = sum_k x[b,k] * (1 - p[b, k>>8]) * Wc[n, k]      (NT GEMM)
__global__ void __launch_bounds__(256) gemm_compress(
    const float* __restrict__ x, const float* __restrict__ Wc)
{
    __shared__ float As[BK][BM];
    __shared__ float Bs[BK][BN];

    int t  = threadIdx.x;
    int ty = t >> 4, tx = t & 15;
    int rowBase = blockIdx.y * BM;
    int colBase = blockIdx.x * BN;

    float acc[8][8];
#pragma unroll
    for (int i = 0; i < 8; i++)
#pragma unroll
        for (int j = 0; j < 8; j++) acc[i][j] = 0.f;

    for (int kt = 0; kt < IN_F; kt += BK) {
        int frag = kt >> 8;
        // A tile: 128 rows x 16 k, scaled by (1-p)
#pragma unroll
        for (int l = 0; l < 2; l++) {
            int idx = t + l * 256;
            int r   = idx >> 2;
            int c4  = (idx & 3) * 4;
            int grow = rowBase + r;
            float sc = 1.0f - g_probs[grow * NFRAG + frag];
            float4 v = *(const float4*)(x + (size_t)grow * IN_F + kt + c4);
            As[c4 + 0][r] = v.x * sc;
            As[c4 + 1][r] = v.y * sc;
            As[c4 + 2][r] = v.z * sc;
            As[c4 + 3][r] = v.w * sc;
        }
        // B tile: Bs[k][n] = Wc[colBase+n][kt+k]  (k contiguous in gmem)
#pragma unroll
        for (int l = 0; l < 2; l++) {
            int idx = t + l * 256;
            int n   = idx >> 2;
            int c4  = (idx & 3) * 4;
            float4 v = *(const float4*)(Wc + (size_t)(colBase + n) * IN_F + kt + c4);
            Bs[c4 + 0][n] = v.x;
            Bs[c4 + 1][n] = v.y;
            Bs[c4 + 2][n] = v.z;
            Bs[c4 + 3][n] = v.w;
        }
        __syncthreads();
#pragma unroll
        for (int kk = 0; kk < BK; kk++) {
            float a[8], bb[8];
            *(float4*)(a)      = *(const float4*)&As[kk][ty * 8];
            *(float4*)(a + 4)  = *(const float4*)&As[kk][ty * 8 + 4];
            *(float4*)(bb)     = *(const float4*)&Bs[kk][tx * 8];
            *(float4*)(bb + 4) = *(const float4*)&Bs[kk][tx * 8 + 4];
#pragma unroll
            for (int i = 0; i < 8; i++)
#pragma unroll
                for (int j = 0; j < 8; j++)
                    acc[i][j] = fmaf(a[i], bb[j], acc[i][j]);
        }
        __syncthreads();
    }
#pragma unroll
    for (int i = 0; i < 8; i++) {
        int grow = rowBase + ty * 8 + i;
#pragma unroll
        for (int j = 0; j < 8; j += 4) {
            float4 v = make_float4(acc[i][j], acc[i][j+1], acc[i][j+2], acc[i][j+3]);
            *(float4*)(g_comp + (size_t)grow * COMP + colBase + tx * 8 + j) = v;
        }
    }
}

// out[b, n] = sum_k x[b,k]*p[b,k>>8]*We[k,n]  +  sum_c C1[b,c]*Wn[n,c]
__global__ void __launch_bounds__(256) gemm_out(
    const float* __restrict__ x, const float* __restrict__ We,
    const float* __restrict__ Wn, float* __restrict__ out)
{
    __shared__ float As[BK][BM];
    __shared__ float Bs[BK][BN];

    int t  = threadIdx.x;
    int ty = t >> 4, tx = t & 15;
    int rowBase = blockIdx.y * BM;
    int colBase = blockIdx.x * BN;

    float acc[8][8];
#pragma unroll
    for (int i = 0; i < 8; i++)
#pragma unroll
        for (int j = 0; j < 8; j++) acc[i][j] = 0.f;

    // ---- Phase 1: expert path, K = 4096, A = x*p, B = We [K, N] row-major ----
    for (int kt = 0; kt < IN_F; kt += BK) {
        int frag = kt >> 8;
#pragma unroll
        for (int l = 0; l < 2; l++) {
            int idx = t + l * 256;
            int r   = idx >> 2;
            int c4  = (idx & 3) * 4;
            int grow = rowBase + r;
            float sc = g_probs[grow * NFRAG + frag];
            float4 v = *(const float4*)(x + (size_t)grow * IN_F + kt + c4);
            As[c4 + 0][r] = v.x * sc;
            As[c4 + 1][r] = v.y * sc;
            As[c4 + 2][r] = v.z * sc;
            As[c4 + 3][r] = v.w * sc;
        }
        // B tile: Bs[k][n] = We[(kt+k)*OUT + colBase + n]  (n contiguous)
#pragma unroll
        for (int l = 0; l < 2; l++) {
            int idx = t + l * 256;
            int r   = idx >> 5;          // 0..15 (k within tile)
            int c   = (idx & 31) * 4;    // 0..124 (n within tile)
            float4 v = *(const float4*)(We + (size_t)(kt + r) * OUT_F + colBase + c);
            *(float4*)&Bs[r][c] = v;
        }
        __syncthreads();
#pragma unroll
        for (int kk = 0; kk < BK; kk++) {
            float a[8], bb[8];
            *(float4*)(a)      = *(const float4*)&As[kk][ty * 8];
            *(float4*)(a + 4)  = *(const float4*)&As[kk][ty * 8 + 4];
            *(float4*)(bb)     = *(const float4*)&Bs[kk][tx * 8];
            *(float4*)(bb + 4) = *(const float4*)&Bs[kk][tx * 8 + 4];
#pragma unroll
            for (int i = 0; i < 8; i++)
#pragma unroll
                for (int j = 0; j < 8; j++)
                    acc[i][j] = fmaf(a[i], bb[j], acc[i][j]);
        }
        __syncthreads();
    }

    // ---- Phase 2: net path, K = 1024, A = C1 (no scale), B = Wn^T ----
    for (int kt = 0; kt < COMP; kt += BK) {
#pragma unroll
        for (int l = 0; l < 2; l++) {
            int idx = t + l * 256;
            int r   = idx >> 2;
            int c4  = (idx & 3) * 4;
            int grow = rowBase + r;
            float4 v = *(const float4*)(g_comp + (size_t)grow * COMP + kt + c4);
            As[c4 + 0][r] = v.x;
            As[c4 + 1][r] = v.y;
            As[c4 + 2][r] = v.z;
            As[c4 + 3][r] = v.w;
        }
        // Bs[k][n] = Wn[colBase+n][kt+k]  (k contiguous in gmem)
#pragma unroll
        for (int l = 0; l < 2; l++) {
            int idx = t + l * 256;
            int n   = idx >> 2;
            int c4  = (idx & 3) * 4;
            float4 v = *(const float4*)(Wn + (size_t)(colBase + n) * COMP + kt + c4);
            Bs[c4 + 0][n] = v.x;
            Bs[c4 + 1][n] = v.y;
            Bs[c4 + 2][n] = v.z;
            Bs[c4 + 3][n] = v.w;
        }
        __syncthreads();
#pragma unroll
        for (int kk = 0; kk < BK; kk++) {
            float a[8], bb[8];
            *(float4*)(a)      = *(const float4*)&As[kk][ty * 8];
            *(float4*)(a + 4)  = *(const float4*)&As[kk][ty * 8 + 4];
            *(float4*)(bb)     = *(const float4*)&Bs[kk][tx * 8];
            *(float4*)(bb + 4) = *(const float4*)&Bs[kk][tx * 8 + 4];
#pragma unroll
            for (int i = 0; i < 8; i++)
#pragma unroll
                for (int j = 0; j < 8; j++)
                    acc[i][j] = fmaf(a[i], bb[j], acc[i][j]);
        }
        __syncthreads();
    }

#pragma unroll
    for (int i = 0; i < 8; i++) {
        int grow = rowBase + ty * 8 + i;
#pragma unroll
        for (int j = 0; j < 8; j += 4) {
            float4 v = make_float4(acc[i][j], acc[i][j+1], acc[i][j+2], acc[i][j+3]);
            *(float4*)(out + (size_t)grow * OUT_F + colBase + tx * 8 + j) = v;
        }
    }
}

// ---------------------------------------------------------------------------
// Launch
// ---------------------------------------------------------------------------
extern "C" void kernel_launch(void* const* d_in, const int* in_sizes, int n_in,
                              void* d_out, int out_size)
{
    const float* x   = (const float*)d_in[0];   // [8192, 4096]
    const float* sel = (const float*)d_in[1];   // [16, 256]
    const float* We  = (const float*)d_in[2];   // [16, 256, 4096] == [4096, 4096]
    const float* Wc  = (const float*)d_in[3];   // [1024, 4096]
    const float* Wn  = (const float*)d_in[4];   // [4096, 1024]
    float* out = (float*)d_out;                 // [8192, 4096]

    gating_kernel<<<B_ROWS, 512>>>(x, sel);

    dim3 gridC(COMP / BN, B_ROWS / BM);         // 8 x 64
    gemm_compress<<<gridC, 256>>>(x, Wc);

    dim3 gridO(OUT_F / BN, B_ROWS / BM);        // 32 x 64
    gemm_out<<<gridO, 256>>>(x, We, Wn, out);
}

// round 6
// speedup vs baseline: 2.6129x; 2.6129x over previous
#include <cuda_runtime.h>
#include <cuda_bf16.h>
#include <cstdint>
#include <math.h>

// ---------------------------------------------------------------------------
// Problem constants
// ---------------------------------------------------------------------------
#define B_ROWS 8192
#define IN_F   4096
#define OUT_F  4096
#define NFRAG  16
#define FS     256
#define COMP   1024

// GEMM tiling
#define BM 128
#define BN 128
#define BK 32            // bf16 elements per stage (64 bytes per row)
#define NSTAGE 3

#define TILE_BYTES  (128 * 64)             // one 128x32 bf16 tile = 8 KB
#define STAGE_BYTES (4 * TILE_BYTES)       // Ah, Al, Bh, Bl = 32 KB
#define SMEM_DYN    (NSTAGE * STAGE_BYTES) // 96 KB

// swizzle: 64B rows, 4x16B chunks; chunk ^= (row>>1)&3  (conflict-free LDSM)
#define SWZ(r, c) ((((c) ^ (((r) >> 1) & 3)) << 4))

// ---------------------------------------------------------------------------
// Scratch (static device globals; no runtime allocation)
// ---------------------------------------------------------------------------
__device__ float g_probs[B_ROWS * NFRAG];

__device__ __align__(16) __nv_bfloat16 g_a_hi [B_ROWS * IN_F];   // x * p
__device__ __align__(16) __nv_bfloat16 g_a_lo [B_ROWS * IN_F];
__device__ __align__(16) __nv_bfloat16 g_m_hi [B_ROWS * IN_F];   // x * (1-p)
__device__ __align__(16) __nv_bfloat16 g_m_lo [B_ROWS * IN_F];
__device__ __align__(16) __nv_bfloat16 g_WeT_hi[OUT_F * IN_F];   // We^T  [N,K]
__device__ __align__(16) __nv_bfloat16 g_WeT_lo[OUT_F * IN_F];
__device__ __align__(16) __nv_bfloat16 g_Wc_hi [COMP * IN_F];    // [N,K]
__device__ __align__(16) __nv_bfloat16 g_Wc_lo [COMP * IN_F];
__device__ __align__(16) __nv_bfloat16 g_Wn_hi [OUT_F * COMP];   // [N,K]
__device__ __align__(16) __nv_bfloat16 g_Wn_lo [OUT_F * COMP];
__device__ __align__(16) __nv_bfloat16 g_c1_hi [B_ROWS * COMP];  // compressed
__device__ __align__(16) __nv_bfloat16 g_c1_lo [B_ROWS * COMP];

// ---------------------------------------------------------------------------
// Helpers (family-safe PTX only: cp.async, ldmatrix, mma.sync — no 'a' features)
// ---------------------------------------------------------------------------
__device__ __forceinline__ uint32_t smem_u32(const void* p) {
    uint32_t a;
    asm("{ .reg .u64 t; cvta.to.shared.u64 t, %1; cvt.u32.u64 %0, t; }"
        : "=r"(a) : "l"(p));
    return a;
}
__device__ __forceinline__ void cp16(uint32_t dst, const void* src) {
    asm volatile("cp.async.cg.shared.global [%0], [%1], 16;" :: "r"(dst), "l"(src));
}
__device__ __forceinline__ void cp_commit() {
    asm volatile("cp.async.commit_group;");
}
__device__ __forceinline__ void cp_wait1() {
    asm volatile("cp.async.wait_group 1;" ::: "memory");
}
__device__ __forceinline__ void ldsm4(uint32_t* f, uint32_t a) {
    asm volatile("ldmatrix.sync.aligned.m8n8.x4.shared.b16 {%0,%1,%2,%3}, [%4];"
                 : "=r"(f[0]), "=r"(f[1]), "=r"(f[2]), "=r"(f[3]) : "r"(a));
}
__device__ __forceinline__ void mma16816(float* d, const uint32_t* a,
                                         uint32_t b0, uint32_t b1) {
    asm volatile(
        "mma.sync.aligned.m16n8k16.row.col.f32.bf16.bf16.f32 "
        "{%0,%1,%2,%3}, {%4,%5,%6,%7}, {%8,%9}, {%0,%1,%2,%3};"
        : "+f"(d[0]), "+f"(d[1]), "+f"(d[2]), "+f"(d[3])
        : "r"(a[0]), "r"(a[1]), "r"(a[2]), "r"(a[3]), "r"(b0), "r"(b1));
}
__device__ __forceinline__ void split2(float f, __nv_bfloat16& h, __nv_bfloat16& l) {
    h = __float2bfloat16(f);
    l = __float2bfloat16(f - __bfloat162float(h));
}
union Pack4 { __nv_bfloat16 h[4]; uint2 u; };

// ---------------------------------------------------------------------------
// Gating: softmax over fragment scores
// ---------------------------------------------------------------------------
__global__ void __launch_bounds__(512) gating_kernel(
    const float* __restrict__ x, const float* __restrict__ sel)
{
    int b = blockIdx.x, t = threadIdx.x;
    int w = t >> 5, lane = t & 31;
    const float* xr = x + (size_t)b * IN_F + w * FS;
    const float* sr = sel + w * FS;
    float acc = 0.f;
#pragma unroll
    for (int j = 0; j < 8; j++) acc += xr[lane + 32*j] * sr[lane + 32*j];
#pragma unroll
    for (int o = 16; o; o >>= 1) acc += __shfl_xor_sync(0xFFFFFFFFu, acc, o);
    __shared__ float s[NFRAG];
    if (lane == 0) s[w] = acc;
    __syncthreads();
    if (t < NFRAG) {
        float m = -INFINITY;
#pragma unroll
        for (int f = 0; f < NFRAG; f++) m = fmaxf(m, s[f]);
        float sum = 0.f;
#pragma unroll
        for (int f = 0; f < NFRAG; f++) sum += __expf(s[f] - m);
        g_probs[b * NFRAG + t] = __expf(s[t] - m) / sum;
    }
}

// ---------------------------------------------------------------------------
// Prescale + split: a = x*p, m = x - a; bf16 hi/lo of both
// ---------------------------------------------------------------------------
__global__ void __launch_bounds__(256) prescale_split(const float* __restrict__ x)
{
    size_t base = ((size_t)blockIdx.x * blockDim.x + threadIdx.x) * 4;
    int b   = (int)(base >> 12);
    int col = (int)(base & 4095);
    float p = g_probs[b * NFRAG + (col >> 8)];
    float4 v = *(const float4*)(x + base);
    float a0 = v.x * p, a1 = v.y * p, a2 = v.z * p, a3 = v.w * p;
    float m0 = v.x - a0, m1 = v.y - a1, m2 = v.z - a2, m3 = v.w - a3;
    Pack4 ah, al, mh, ml;
    split2(a0, ah.h[0], al.h[0]); split2(a1, ah.h[1], al.h[1]);
    split2(a2, ah.h[2], al.h[2]); split2(a3, ah.h[3], al.h[3]);
    split2(m0, mh.h[0], ml.h[0]); split2(m1, mh.h[1], ml.h[1]);
    split2(m2, mh.h[2], ml.h[2]); split2(m3, mh.h[3], ml.h[3]);
    *(uint2*)(g_a_hi + base) = ah.u;  *(uint2*)(g_a_lo + base) = al.u;
    *(uint2*)(g_m_hi + base) = mh.u;  *(uint2*)(g_m_lo + base) = ml.u;
}

// ---------------------------------------------------------------------------
// Transpose + split We [K,N] -> WeT [N,K]
// ---------------------------------------------------------------------------
__global__ void __launch_bounds__(256) transpose_split_we(const float* __restrict__ We)
{
    __shared__ float tile[32][33];
    int k0 = blockIdx.y * 32, n0 = blockIdx.x * 32;
    int tx = threadIdx.x, ty = threadIdx.y;
#pragma unroll
    for (int r = 0; r < 4; r++)
        tile[ty + r*8][tx] = We[(size_t)(k0 + ty + r*8) * OUT_F + n0 + tx];
    __syncthreads();
#pragma unroll
    for (int r = 0; r < 4; r++) {
        float v = tile[tx][ty + r*8];
        __nv_bfloat16 h, l; split2(v, h, l);
        size_t o = (size_t)(n0 + ty + r*8) * IN_F + k0 + tx;
        g_WeT_hi[o] = h;
        g_WeT_lo[o] = l;
    }
}

// ---------------------------------------------------------------------------
// Generic split (Wc / Wn) — already [N,K] K-contiguous
// ---------------------------------------------------------------------------
__global__ void __launch_bounds__(256) split_generic(const float* __restrict__ src, int which)
{
    size_t base = ((size_t)blockIdx.x * blockDim.x + threadIdx.x) * 4;
    __nv_bfloat16* hp = which ? g_Wn_hi : g_Wc_hi;
    __nv_bfloat16* lp = which ? g_Wn_lo : g_Wc_lo;
    float4 v = *(const float4*)(src + base);
    Pack4 h, l;
    split2(v.x, h.h[0], l.h[0]); split2(v.y, h.h[1], l.h[1]);
    split2(v.z, h.h[2], l.h[2]); split2(v.w, h.h[3], l.h[3]);
    *(uint2*)(hp + base) = h.u;
    *(uint2*)(lp + base) = l.u;
}

// ---------------------------------------------------------------------------
// GEMM core pieces
// ---------------------------------------------------------------------------
struct SegP {
    const __nv_bfloat16 *Ah, *Al, *Bh, *Bl;
    int ldA, ldB, nt;    // nt = number of BK tiles in this segment
};

// stage load: 4 tiles (Ah, Al, Bh, Bl), each 128 rows x 32 bf16, swizzled
__device__ __forceinline__ void load_stage(uint32_t st, const SegP& sg,
                                           int rowBase, int colBase, int kt)
{
    int t = threadIdx.x;
#pragma unroll
    for (int i = 0; i < 2; i++) {
        int id = t + i * 256;
        int r  = id >> 2;
        int c  = id & 3;
        uint32_t off = (uint32_t)(r * 64 + SWZ(r, c));
        size_t ga = (size_t)(rowBase + r) * sg.ldA + kt + c * 8;
        size_t gb = (size_t)(colBase + r) * sg.ldB + kt + c * 8;
        cp16(st + off,                  sg.Ah + ga);
        cp16(st + TILE_BYTES + off,     sg.Al + ga);
        cp16(st + 2 * TILE_BYTES + off, sg.Bh + gb);
        cp16(st + 3 * TILE_BYTES + off, sg.Bl + gb);
    }
}

// compute one BK=32 stage: 3-product bf16 (hi*hi + hi*lo + lo*hi)
__device__ __forceinline__ void compute_stage(uint32_t st, float acc[4][4][4],
                                              int wm, int wn, int lane)
{
#pragma unroll
    for (int kk = 0; kk < 2; kk++) {                 // k sub-steps of 16
        int cbase = kk * 2 + (lane >> 4);            // 16B chunk index (0..3)
        uint32_t ah[4][4], al[4][4], bh[2][4], bl[2][4];
#pragma unroll
        for (int mi = 0; mi < 4; mi++) {
            int r = wm * 64 + mi * 16 + (lane & 15);
            uint32_t off = (uint32_t)(r * 64 + SWZ(r, cbase));
            ldsm4(ah[mi], st + off);
            ldsm4(al[mi], st + TILE_BYTES + off);
        }
#pragma unroll
        for (int ni = 0; ni < 2; ni++) {
            int r = wn * 32 + ni * 16 + (lane & 15);
            uint32_t off = (uint32_t)(r * 64 + SWZ(r, cbase));
            ldsm4(bh[ni], st + 2 * TILE_BYTES + off);
            ldsm4(bl[ni], st + 3 * TILE_BYTES + off);
        }
#pragma unroll
        for (int mi = 0; mi < 4; mi++)
#pragma unroll
            for (int ng = 0; ng < 4; ng++) {
                int ni = ng >> 1, s = ng & 1;
                mma16816(acc[mi][ng], ah[mi], bh[ni][s], bh[ni][s + 2]);
                mma16816(acc[mi][ng], ah[mi], bl[ni][s], bl[ni][s + 2]);
                mma16816(acc[mi][ng], al[mi], bh[ni][s], bh[ni][s + 2]);
            }
    }
}

// pipelined mainloop over (up to 2) segments; fills acc
__device__ __forceinline__ void run_mainloop(uint32_t sb, const SegP* segs, int nseg,
                                             int rowBase, int colBase,
                                             float acc[4][4][4])
{
    int lane = threadIdx.x & 31, wid = threadIdx.x >> 5;
    int wm = wid >> 2, wn = wid & 3;

    int ntTot = 0;
    for (int s = 0; s < nseg; s++) ntTot += segs[s].nt;

    // tile index -> (seg, kt) resolver
    auto issue = [&](int tile, int stageIdx) {
        int i = tile, s = 0;
        while (s < nseg - 1 && i >= segs[s].nt) { i -= segs[s].nt; s++; }
        load_stage(sb + stageIdx * STAGE_BYTES, segs[s], rowBase, colBase, i * BK);
    };

    issue(0, 0); cp_commit();
    if (ntTot > 1) issue(1, 1);
    cp_commit();

    for (int it = 0; it < ntTot; it++) {
        cp_wait1();
        __syncthreads();
        if (it + 2 < ntTot) issue(it + 2, (it + 2) % NSTAGE);
        cp_commit();
        compute_stage(sb + (it % NSTAGE) * STAGE_BYTES, acc, wm, wn, lane);
        __syncthreads();
    }
}

// ---------------------------------------------------------------------------
// GEMM 1: compressed = (x - a) @ Wc^T  -> split to c1 hi/lo
// ---------------------------------------------------------------------------
__global__ void __launch_bounds__(256, 1) gemm_compress_mma()
{
    extern __shared__ __align__(128) char smem[];
    uint32_t sb = smem_u32(smem);
    int rowBase = blockIdx.y * BM, colBase = blockIdx.x * BN;

    float acc[4][4][4];
#pragma unroll
    for (int a = 0; a < 4; a++)
#pragma unroll
        for (int b = 0; b < 4; b++)
#pragma unroll
            for (int c = 0; c < 4; c++) acc[a][b][c] = 0.f;

    SegP segs[1] = { { g_m_hi, g_m_lo, g_Wc_hi, g_Wc_lo, IN_F, IN_F, IN_F / BK } };
    run_mainloop(sb, segs, 1, rowBase, colBase, acc);

    int lane = threadIdx.x & 31, wid = threadIdx.x >> 5;
    int wm = wid >> 2, wn = wid & 3;
#pragma unroll
    for (int mi = 0; mi < 4; mi++)
#pragma unroll
        for (int ng = 0; ng < 4; ng++) {
            int r0 = rowBase + wm * 64 + mi * 16 + (lane >> 2);
            int c0 = colBase + wn * 32 + ng * 8 + (lane & 3) * 2;
            __nv_bfloat16 h0, l0, h1, l1;
            split2(acc[mi][ng][0], h0, l0); split2(acc[mi][ng][1], h1, l1);
            *(__nv_bfloat162*)(g_c1_hi + (size_t)r0 * COMP + c0) = __nv_bfloat162(h0, h1);
            *(__nv_bfloat162*)(g_c1_lo + (size_t)r0 * COMP + c0) = __nv_bfloat162(l0, l1);
            split2(acc[mi][ng][2], h0, l0); split2(acc[mi][ng][3], h1, l1);
            *(__nv_bfloat162*)(g_c1_hi + (size_t)(r0 + 8) * COMP + c0) = __nv_bfloat162(h0, h1);
            *(__nv_bfloat162*)(g_c1_lo + (size_t)(r0 + 8) * COMP + c0) = __nv_bfloat162(l0, l1);
        }
}

// ---------------------------------------------------------------------------
// GEMM 2 (fused): out = a @ We  +  c1 @ Wn^T
// ---------------------------------------------------------------------------
__global__ void __launch_bounds__(256, 1) gemm_out_mma(float* __restrict__ out)
{
    extern __shared__ __align__(128) char smem[];
    uint32_t sb = smem_u32(smem);
    int rowBase = blockIdx.y * BM, colBase = blockIdx.x * BN;

    float acc[4][4][4];
#pragma unroll
    for (int a = 0; a < 4; a++)
#pragma unroll
        for (int b = 0; b < 4; b++)
#pragma unroll
            for (int c = 0; c < 4; c++) acc[a][b][c] = 0.f;

    SegP segs[2] = {
        { g_a_hi,  g_a_lo,  g_WeT_hi, g_WeT_lo, IN_F, IN_F, IN_F / BK },
        { g_c1_hi, g_c1_lo, g_Wn_hi,  g_Wn_lo,  COMP, COMP, COMP / BK },
    };
    run_mainloop(sb, segs, 2, rowBase, colBase, acc);

    int lane = threadIdx.x & 31, wid = threadIdx.x >> 5;
    int wm = wid >> 2, wn = wid & 3;
#pragma unroll
    for (int mi = 0; mi < 4; mi++)
#pragma unroll
        for (int ng = 0; ng < 4; ng++) {
            int r0 = rowBase + wm * 64 + mi * 16 + (lane >> 2);
            int c0 = colBase + wn * 32 + ng * 8 + (lane & 3) * 2;
            *(float2*)(out + (size_t)r0 * OUT_F + c0) =
                make_float2(acc[mi][ng][0], acc[mi][ng][1]);
            *(float2*)(out + (size_t)(r0 + 8) * OUT_F + c0) =
                make_float2(acc[mi][ng][2], acc[mi][ng][3]);
        }
}

// ---------------------------------------------------------------------------
// Launch
// ---------------------------------------------------------------------------
extern "C" void kernel_launch(void* const* d_in, const int* in_sizes, int n_in,
                              void* d_out, int out_size)
{
    const float* x   = (const float*)d_in[0];   // [8192, 4096]
    const float* sel = (const float*)d_in[1];   // [16, 256]
    const float* We  = (const float*)d_in[2];   // [4096, 4096]  (K,N)
    const float* Wc  = (const float*)d_in[3];   // [1024, 4096]  (N,K)
    const float* Wn  = (const float*)d_in[4];   // [4096, 1024]  (N,K)
    float* out = (float*)d_out;                 // [8192, 4096]

    cudaFuncSetAttribute(gemm_compress_mma, cudaFuncAttributeMaxDynamicSharedMemorySize, SMEM_DYN);
    cudaFuncSetAttribute(gemm_out_mma,      cudaFuncAttributeMaxDynamicSharedMemorySize, SMEM_DYN);

    gating_kernel<<<B_ROWS, 512>>>(x, sel);
    prescale_split<<<(B_ROWS * (IN_F / 4)) / 256, 256>>>(x);
    transpose_split_we<<<dim3(OUT_F / 32, IN_F / 32), dim3(32, 8)>>>(We);
    split_generic<<<(COMP * (IN_F / 4)) / 256, 256>>>(Wc, 0);
    split_generic<<<(OUT_F * (COMP / 4)) / 256, 256>>>(Wn, 1);

    gemm_compress_mma<<<dim3(COMP / BN, B_ROWS / BM), 256, SMEM_DYN>>>();
    gemm_out_mma<<<dim3(OUT_F / BN, B_ROWS / BM), 256, SMEM_DYN>>>(out);
}